// round 10
// baseline (speedup 1.0000x reference)
#include <cuda_runtime.h>
#include <cuda_fp16.h>
#include <cstdint>

// ---------------- problem constants ----------------
#define NN    4096      // nodes
#define BB    32        // batch
#define CC    64        // channels in/out
#define DE    16        // embedding dim
#define NBJ   2048      // B*C  (columns of the big GEMM)

// ---------------- device scratch (no allocs allowed) ----------------
__device__ __align__(256) __half g_A [(size_t)NN * NN];    // fp16(S), 32 MB
__device__ __align__(256) __half g_B [(size_t)NBJ * NN];   // fp16(x^T) [j][k], 16 MB
__device__ __align__(256) float  g_Y [(size_t)NN * NBJ];   // S @ XT, 32 MB
__device__ __align__(256) __half g_W16[(size_t)NN * 8192]; // per-node weights fp16, 67 MB
__device__ float g_sd[NN];
__device__ float g_scale[NN];

// ---------------- fast exp: 6-FFMA exp2 poly + exponent bit trick -------------
__device__ __forceinline__ float fast_exp(float x){
    float t = fminf(fmaxf(x * 1.4426950408889634f, -125.f), 125.f);
    float fi = floorf(t);
    float f = t - fi;
    float p =            1.3393720e-3f;
    p = fmaf(p, f, 9.6181291e-3f);
    p = fmaf(p, f, 5.5504109e-2f);
    p = fmaf(p, f, 2.4022651e-1f);
    p = fmaf(p, f, 6.9314718e-1f);
    p = fmaf(p, f, 1.0f);
    return __int_as_float(__float_as_int(p) + ((int)fi << 23));
}

// ---------------- PTX helpers (base ISA: ldmatrix / mma.sync / cp.async) ------
__device__ __forceinline__ uint32_t smem_u32(const void* p){
    uint32_t a;
    asm("{ .reg .u64 t; cvta.to.shared.u64 t, %1; cvt.u32.u64 %0, t; }" : "=r"(a) : "l"(p));
    return a;
}
#define LDSM_X4(R, addr) \
    asm volatile("ldmatrix.sync.aligned.m8n8.x4.shared.b16 {%0,%1,%2,%3}, [%4];" \
        : "=r"((R)[0]), "=r"((R)[1]), "=r"((R)[2]), "=r"((R)[3]) : "r"(addr))
#define MMA16816(D, A, B0, B1) \
    asm volatile("mma.sync.aligned.m16n8k16.row.col.f32.f16.f16.f32 " \
        "{%0,%1,%2,%3}, {%4,%5,%6,%7}, {%8,%9}, {%0,%1,%2,%3};" \
        : "+f"((D)[0]), "+f"((D)[1]), "+f"((D)[2]), "+f"((D)[3]) \
        : "r"((A)[0]), "r"((A)[1]), "r"((A)[2]), "r"((A)[3]), "r"(B0), "r"(B1))
#define CP_ASYNC16(dst, src) \
    asm volatile("cp.async.cg.shared.global [%0], [%1], 16;" :: "r"(dst), "l"(src) : "memory")
#define CP_COMMIT() asm volatile("cp.async.commit_group;" ::: "memory")

// ---------------- reductions ----------------
__device__ __forceinline__ float warpSum(float v){
#pragma unroll
    for (int o = 16; o; o >>= 1) v += __shfl_xor_sync(0xffffffffu, v, o);
    return v;
}
__device__ __forceinline__ float blockSum(float v, float* red){
    v = warpSum(v);
    int lane = threadIdx.x & 31, w = threadIdx.x >> 5;
    if (lane == 0) red[w] = v;
    __syncthreads();
    float r = 0.f;
#pragma unroll
    for (int i = 0; i < 8; i++) r += red[i];
    __syncthreads();
    return r;
}

// ---------------- 0: zero scale accumulator ----------------
__global__ void k_zero(){
    int i = blockIdx.x * 256 + threadIdx.x;
    if (i < NN) g_scale[i] = 0.f;
}

// ---------------- 1: rowsums of (adj + 0.5 I) -> g_sd ----------------
__global__ __launch_bounds__(256) void k_rowsum(const float* __restrict__ adj){
    __shared__ float red[8];
    int n = blockIdx.x;
    const float* row = adj + (size_t)n * NN;
    float s = 0.f;
    for (int m = threadIdx.x; m < NN; m += 256) s += row[m];
    if (threadIdx.x == 0) s += 0.5f;
    s = blockSum(s, red);
    if (threadIdx.x == 0) g_sd[n] = rsqrtf(s);
}

// ---------------- 2: double row-softmax of sym-normed adj, column sums --------
__global__ __launch_bounds__(256) void k_scale(const float* __restrict__ adj){
    __shared__ float rowbuf[NN];
    __shared__ float acc[NN];
    __shared__ float red[8];
    int tid = threadIdx.x;
    for (int m = tid; m < NN; m += 256) acc[m] = 0.f;
    __syncthreads();
    for (int r = 0; r < 16; r++){
        int n = blockIdx.x * 16 + r;
        const float* row = adj + (size_t)n * NN;
        float sdn = g_sd[n];
        float ls = 0.f;
        for (int m = tid; m < NN; m += 256){
            float w = row[m] + ((m == n) ? 0.5f : 0.f);
            float e = fast_exp(sdn * w * g_sd[m]);
            rowbuf[m] = e; ls += e;
        }
        float inv = 1.f / blockSum(ls, red);
        float ls2 = 0.f;
        for (int m = tid; m < NN; m += 256){
            float e2 = fast_exp(rowbuf[m] * inv);
            rowbuf[m] = e2; ls2 += e2;
        }
        float inv2 = 1.f / blockSum(ls2, red);
        for (int m = tid; m < NN; m += 256) acc[m] += rowbuf[m] * inv2;
        __syncthreads();
    }
    for (int m = tid; m < NN; m += 256) atomicAdd(&g_scale[m], acc[m]);
}

// ---------------- 3: S = softmax(relu(E E^T)) -> fp16 -------------------------
#define DYN_ROWS 4
#define DYN_SMEM (DYN_ROWS * NN * 4)
__global__ __launch_bounds__(256) void k_dyn(const float* __restrict__ E){
    extern __shared__ float rb[];                 // [DYN_ROWS][NN]
    __shared__ float er[DYN_ROWS][DE];
    __shared__ float red[8];
    int tid = threadIdx.x;
    int n0 = blockIdx.x * DYN_ROWS;
    if (tid < DYN_ROWS * DE) er[tid / DE][tid % DE] = E[(n0 + tid / DE) * DE + (tid % DE)];
    __syncthreads();
    float ls[DYN_ROWS] = {0.f, 0.f, 0.f, 0.f};
    for (int m = tid; m < NN; m += 256){
        const float4* ep = (const float4*)(E + (size_t)m * DE);
        float4 e0 = ep[0], e1 = ep[1], e2 = ep[2], e3 = ep[3];
        float em[16] = { e0.x,e0.y,e0.z,e0.w, e1.x,e1.y,e1.z,e1.w,
                         e2.x,e2.y,e2.z,e2.w, e3.x,e3.y,e3.z,e3.w };
#pragma unroll
        for (int r = 0; r < DYN_ROWS; r++){
            float d = 0.f;
#pragma unroll
            for (int k = 0; k < DE; k++) d += em[k] * er[r][k];
            float e = fast_exp(fmaxf(d, 0.f));
            rb[r * NN + m] = e;
            ls[r] += e;
        }
    }
    float inv[DYN_ROWS];
#pragma unroll
    for (int r = 0; r < DYN_ROWS; r++) inv[r] = 1.f / blockSum(ls[r], red);
#pragma unroll
    for (int r = 0; r < DYN_ROWS; r++){
        __half* oh = g_A + (size_t)(n0 + r) * NN;
        for (int m = tid; m < NN; m += 256)
            oh[m] = __float2half(rb[r * NN + m] * inv[r]);
    }
}

// ---------------- 4: x [B,N,C] -> B-operand [j=b*64+c][k] fp16 ----------------
__global__ __launch_bounds__(256) void k_xsplit(const float* __restrict__ x){
    __shared__ float xs[64][65];
    int b  = blockIdx.x >> 6;
    int kc = blockIdx.x & 63;
    int tid = threadIdx.x;
    const float* src = x + ((size_t)b * NN + kc * 64) * 64;
    for (int t = tid; t < 1024; t += 256){
        int kk = t >> 4, c4 = t & 15;
        float4 v = ((const float4*)src)[(size_t)kk * 16 + c4];
        xs[kk][c4 * 4 + 0] = v.x; xs[kk][c4 * 4 + 1] = v.y;
        xs[kk][c4 * 4 + 2] = v.z; xs[kk][c4 * 4 + 3] = v.w;
    }
    __syncthreads();
    int c = tid >> 2, q = tid & 3;
    union { __half h[16]; uint4 u[2]; } uh;
#pragma unroll
    for (int i = 0; i < 16; i++)
        uh.h[i] = __float2half(xs[q * 16 + i][c]);
    size_t off = ((size_t)(b * 64 + c)) * NN + kc * 64 + q * 16;
    *(uint4*)(g_B + off) = uh.u[0]; *(uint4*)(g_B + off + 8) = uh.u[1];
}

// ---------------- 5: per-node weights -> fp16 ---------------------------------
__global__ __launch_bounds__(256) void k_wgen(const float* __restrict__ E,
                                              const float* __restrict__ wp){
    __shared__ float wpc[DE * 512];
    __shared__ float es[128 * DE];
    int tid = threadIdx.x;
    int c0 = blockIdx.x * 512;
    int n0 = blockIdx.y * 128;
    for (int t = tid; t < DE * 512; t += 256){
        int d = t >> 9, j = t & 511;
        wpc[t] = wp[(size_t)d * 8192 + c0 + j];
    }
    for (int t = tid; t < 128 * DE; t += 256) es[t] = E[(size_t)n0 * DE + t];
    __syncthreads();
    for (int t = tid; t < 128 * 256; t += 256){
        int nl = t >> 8, j2 = (t & 255) * 2;
        float s0 = 0.f, s1 = 0.f;
#pragma unroll
        for (int d = 0; d < DE; d++){
            float e = es[nl * DE + d];
            s0 += e * wpc[d * 512 + j2];
            s1 += e * wpc[d * 512 + j2 + 1];
        }
        *(__half2*)&g_W16[(size_t)(n0 + nl) * 8192 + c0 + j2] =
            __floats2half2_rn(s0, s1);
    }
}

// ---------------- 6: HMMA GEMM  Y = S @ XT  -----------------------------------
// Block 256x128, 8 warps (4m x 2n), warp tile 64x64, K-chunk 32, 4-stage cp.async.
// A tile 256x80B, B tile 128x80B (64B data + 16B pad) -> ldmatrix conflict-free.
#define A_TILE_B   20480            // 256 * 80
#define B_TILE_B   10240            // 128 * 80
#define STAGE_BYTES (A_TILE_B + B_TILE_B)
#define GEMM_SMEM   (4 * STAGE_BYTES)

__global__ __launch_bounds__(256, 1) void k_gemm_mma(){
    extern __shared__ __align__(1024) char smem[];
    uint32_t sm = smem_u32(smem);
    int tid = threadIdx.x, wid = tid >> 5, lane = tid & 31;
    int bx = blockIdx.x, by = blockIdx.y;

    const char* pA = (const char*)g_A + (size_t)(by * 256) * (NN * 2);
    const char* pB = (const char*)g_B + (size_t)(bx * 128) * (NN * 2);

    int m0 = (wid & 3) * 64;          // 4 m-warps cover 256 rows
    int n0 = (wid >> 2) * 64;         // 2 n-warps cover 128 cols

    // ldmatrix lane addressing (byte offsets within a tile)
    uint32_t a_off = (uint32_t)((m0 + (lane & 15)) * 80 + ((lane >> 4) << 4));
    uint32_t b_off = (uint32_t)((n0 + ((lane >> 4) << 3) + (lane & 7)) * 80
                                + (((lane >> 3) & 1) << 4));

    auto load_stage = [&](int buf, int kblk){
        uint32_t sbase = sm + (uint32_t)buf * STAGE_BYTES;
        size_t kb = (size_t)kblk * 64;             // 32 fp16 = 64B per row chunk
#pragma unroll
        for (int i = 0; i < 6; i++){
            int id = tid + i * 256;                // 0..1535
            if (id < 1024){                        // A: 256 rows x 4 chunks
                int r = id >> 2, c = id & 3;
                const char* src = pA + (size_t)r * (NN * 2) + kb + (size_t)c * 16;
                uint32_t dst = sbase + (uint32_t)(r * 80 + c * 16);
                CP_ASYNC16(dst, src);
            } else {                               // B: 128 rows x 4 chunks
                int id2 = id - 1024;
                int r = id2 >> 2, c = id2 & 3;
                const char* src = pB + (size_t)r * (NN * 2) + kb + (size_t)c * 16;
                uint32_t dst = sbase + A_TILE_B + (uint32_t)(r * 80 + c * 16);
                CP_ASYNC16(dst, src);
            }
        }
        CP_COMMIT();
    };

    float acc[4][8][4];
#pragma unroll
    for (int tm = 0; tm < 4; tm++)
#pragma unroll
        for (int nb = 0; nb < 8; nb++)
#pragma unroll
            for (int q = 0; q < 4; q++) acc[tm][nb][q] = 0.f;

    load_stage(0, 0);
    load_stage(1, 1);
    load_stage(2, 2);

    const int NIT = NN / 32;          // 128 iterations
    for (int s = 0; s < NIT; s++){
        if (s + 3 < NIT)      asm volatile("cp.async.wait_group 2;" ::: "memory");
        else if (s + 2 < NIT) asm volatile("cp.async.wait_group 1;" ::: "memory");
        else                  asm volatile("cp.async.wait_group 0;" ::: "memory");
        __syncthreads();
        if (s + 3 < NIT) load_stage((s + 3) & 3, s + 3);

        uint32_t st = sm + (uint32_t)(s & 3) * STAGE_BYTES;
        uint32_t aA = st + a_off;
        uint32_t aB = st + A_TILE_B + b_off;
#pragma unroll
        for (int ks = 0; ks < 2; ks++){
            uint32_t ko = (uint32_t)(ks * 32);
            uint32_t Af[4][4], Bf[4][4];
#pragma unroll
            for (int t = 0; t < 4; t++)
                LDSM_X4(Af[t], aA + (uint32_t)(t * 1280) + ko);   // +16 rows * 80B
#pragma unroll
            for (int p = 0; p < 4; p++)
                LDSM_X4(Bf[p], aB + (uint32_t)(p * 1280) + ko);
#pragma unroll
            for (int tm = 0; tm < 4; tm++)
#pragma unroll
                for (int nb = 0; nb < 8; nb++){
                    int p = nb >> 1, h = (nb & 1) * 2;
                    MMA16816(acc[tm][nb], Af[tm], Bf[p][h], Bf[p][h + 1]);
                }
        }
    }

    int gr = lane >> 2, gc = (lane & 3) * 2;
#pragma unroll
    for (int tm = 0; tm < 4; tm++){
        int row = by * 256 + m0 + tm * 16 + gr;
        float* y0 = g_Y + (size_t)row * NBJ + bx * 128 + n0 + gc;
        float* y1 = y0 + 8 * NBJ;
#pragma unroll
        for (int nb = 0; nb < 8; nb++){
            *(float2*)(y0 + nb * 8) = make_float2(acc[tm][nb][0], acc[tm][nb][1]);
            *(float2*)(y1 + nb * 8) = make_float2(acc[tm][nb][2], acc[tm][nb][3]);
        }
    }
}

// ---------------- 7: fused gconv + static branch ------------------------------
#define FIN_W   0
#define FIN_LW  8192
#define FIN_XS  (FIN_LW + 4096)
#define FIN_YS  (FIN_XS + 1024)
#define FIN_SMEM ((FIN_YS + 1024) * 4)
__global__ __launch_bounds__(256) void k_final(const float* __restrict__ x,
                                               const float* __restrict__ E,
                                               const float* __restrict__ bp,
                                               const float* __restrict__ lw,
                                               const float* __restrict__ lb,
                                               float* __restrict__ out){
    extern __shared__ float sf[];
    float* W  = sf + FIN_W;
    float* LW = sf + FIN_LW;
    float4* Xs = (float4*)(sf + FIN_XS);
    float4* Ys = (float4*)(sf + FIN_YS);
    __shared__ float bias_s[CC];
    __shared__ float lbs[CC];
    __shared__ float e_s[DE];
    int n = blockIdx.x, tid = threadIdx.x;
    if (tid < DE) e_s[tid] = E[(size_t)n * DE + tid];
    if (tid < CC) lbs[tid] = lb[tid];
    {
        const uint4* src = (const uint4*)(g_W16 + (size_t)n * 8192);
        for (int t = tid; t < 1024; t += 256){
            uint4 u = src[t];
            __half2* hp = (__half2*)&u;
            float* dst = W + t * 8;
#pragma unroll
            for (int q = 0; q < 4; q++){
                float2 f = __half22float2(hp[q]);
                dst[q * 2] = f.x; dst[q * 2 + 1] = f.y;
            }
        }
    }
    for (int idx = tid; idx < CC * CC; idx += 256){
        int o = idx & 63, i = idx >> 6;
        LW[i * 64 + o] = lw[o * 64 + i];
    }
    __syncthreads();
    if (tid < CC){
        float s = 0.f;
#pragma unroll
        for (int d = 0; d < DE; d++) s += e_s[d] * bp[d * 64 + tid];
        bias_s[tid] = s;
    }
    float scale_n = g_scale[n];
    int o = tid & 63, g = tid >> 6;
    for (int pass = 0; pass < 2; pass++){
        int bbase = pass * 16;
        __syncthreads();
        {
            int b = tid >> 4, i4 = tid & 15;
            Xs[b * 16 + i4] = *(const float4*)&x[((size_t)(bbase + b) * NN + n) * 64 + i4 * 4];
            Ys[b * 16 + i4] = *(const float4*)&g_Y[(size_t)n * NBJ + (bbase + b) * 64 + i4 * 4];
        }
        __syncthreads();
        float accg[4] = {0.f, 0.f, 0.f, 0.f};
        float accs[4] = {0.f, 0.f, 0.f, 0.f};
#pragma unroll 4
        for (int i4 = 0; i4 < 16; i4++){
            int ib = i4 * 4;
            float w00 = W[(ib + 0) * 64 + o], w01 = W[(ib + 1) * 64 + o];
            float w02 = W[(ib + 2) * 64 + o], w03 = W[(ib + 3) * 64 + o];
            float w10 = W[4096 + (ib + 0) * 64 + o], w11 = W[4096 + (ib + 1) * 64 + o];
            float w12 = W[4096 + (ib + 2) * 64 + o], w13 = W[4096 + (ib + 3) * 64 + o];
            float l0 = LW[(ib + 0) * 64 + o], l1 = LW[(ib + 1) * 64 + o];
            float l2 = LW[(ib + 2) * 64 + o], l3 = LW[(ib + 3) * 64 + o];
#pragma unroll
            for (int t = 0; t < 4; t++){
                float4 xv = Xs[(g + 4 * t) * 16 + i4];
                float4 yv = Ys[(g + 4 * t) * 16 + i4];
                float a = accg[t];
                a = fmaf(xv.x, w00, a); a = fmaf(xv.y, w01, a);
                a = fmaf(xv.z, w02, a); a = fmaf(xv.w, w03, a);
                a = fmaf(yv.x, w10, a); a = fmaf(yv.y, w11, a);
                a = fmaf(yv.z, w12, a); a = fmaf(yv.w, w13, a);
                accg[t] = a;
                float s = accs[t];
                s = fmaf(xv.x, l0, s); s = fmaf(xv.y, l1, s);
                s = fmaf(xv.z, l2, s); s = fmaf(xv.w, l3, s);
                accs[t] = s;
            }
        }
#pragma unroll
        for (int t = 0; t < 4; t++){
            int b = bbase + g + 4 * t;
            float xs = fmaf(scale_n, accs[t], lbs[o]);
            float sg = 1.f / (1.f + fast_exp(-xs));
            out[((size_t)b * NN + n) * 64 + o] = accg[t] + bias_s[o] + sg * xs;
        }
    }
}

// ---------------- launch ----------------
extern "C" void kernel_launch(void* const* d_in, const int* in_sizes, int n_in,
                              void* d_out, int out_size){
    const float* x   = (const float*)d_in[0];
    const float* E   = (const float*)d_in[1];
    const float* wp  = (const float*)d_in[2];
    const float* bp  = (const float*)d_in[3];
    const float* lw  = (const float*)d_in[4];
    const float* lb  = (const float*)d_in[5];
    const float* adj = (const float*)d_in[6];
    float* out = (float*)d_out;
    (void)in_sizes; (void)n_in; (void)out_size;

    cudaFuncSetAttribute(k_gemm_mma, cudaFuncAttributeMaxDynamicSharedMemorySize, GEMM_SMEM);
    cudaFuncSetAttribute(k_dyn,      cudaFuncAttributeMaxDynamicSharedMemorySize, DYN_SMEM);
    cudaFuncSetAttribute(k_final,    cudaFuncAttributeMaxDynamicSharedMemorySize, FIN_SMEM);

    k_zero    <<<16, 256>>>();
    k_rowsum  <<<NN, 256>>>(adj);
    k_scale   <<<NN / 16, 256>>>(adj);
    k_dyn     <<<NN / DYN_ROWS, 256, DYN_SMEM>>>(E);
    k_xsplit  <<<BB * 64, 256>>>(x);
    k_wgen    <<<dim3(16, 32), 256>>>(E, wp);
    k_gemm_mma<<<dim3(NBJ / 128, NN / 256), 256, GEMM_SMEM>>>();
    k_final   <<<NN, 256, FIN_SMEM>>>(x, E, bp, lw, lb, out);
}

// round 13
// speedup vs baseline: 1.0483x; 1.0483x over previous
#include <cuda_runtime.h>
#include <cuda_fp16.h>
#include <cstdint>

// ---------------- problem constants ----------------
#define NN    4096      // nodes
#define BB    32        // batch
#define CC    64        // channels in/out
#define DE    16        // embedding dim
#define NBJ   2048      // B*C  (columns of the big GEMM)

// ---------------- device scratch (no allocs allowed) ----------------
__device__ __align__(256) __half g_A [(size_t)NN * NN];    // fp16(S), 32 MB
__device__ __align__(256) __half g_B [(size_t)NBJ * NN];   // fp16(x^T) [j][k], 16 MB
__device__ __align__(256) float  g_Y [(size_t)NN * NBJ];   // S @ XT, 32 MB
__device__ __align__(256) __half g_W16[(size_t)NN * 8192]; // per-node weights fp16, 67 MB
__device__ float g_sd[NN];
__device__ float g_scale[NN];

// ---------------- fast exp: 6-FFMA exp2 poly + exponent bit trick -------------
__device__ __forceinline__ float fast_exp(float x){
    float t = fminf(fmaxf(x * 1.4426950408889634f, -125.f), 125.f);
    float fi = floorf(t);
    float f = t - fi;
    float p =            1.3393720e-3f;
    p = fmaf(p, f, 9.6181291e-3f);
    p = fmaf(p, f, 5.5504109e-2f);
    p = fmaf(p, f, 2.4022651e-1f);
    p = fmaf(p, f, 6.9314718e-1f);
    p = fmaf(p, f, 1.0f);
    return __int_as_float(__float_as_int(p) + ((int)fi << 23));
}

// ---------------- PTX helpers (base ISA: ldmatrix / mma.sync / cp.async) ------
__device__ __forceinline__ uint32_t smem_u32(const void* p){
    uint32_t a;
    asm("{ .reg .u64 t; cvta.to.shared.u64 t, %1; cvt.u32.u64 %0, t; }" : "=r"(a) : "l"(p));
    return a;
}
#define LDSM_X4(R, addr) \
    asm volatile("ldmatrix.sync.aligned.m8n8.x4.shared.b16 {%0,%1,%2,%3}, [%4];" \
        : "=r"((R)[0]), "=r"((R)[1]), "=r"((R)[2]), "=r"((R)[3]) : "r"(addr))
#define MMA16816(D, A, B0, B1) \
    asm volatile("mma.sync.aligned.m16n8k16.row.col.f32.f16.f16.f32 " \
        "{%0,%1,%2,%3}, {%4,%5,%6,%7}, {%8,%9}, {%0,%1,%2,%3};" \
        : "+f"((D)[0]), "+f"((D)[1]), "+f"((D)[2]), "+f"((D)[3]) \
        : "r"((A)[0]), "r"((A)[1]), "r"((A)[2]), "r"((A)[3]), "r"(B0), "r"(B1))
#define CP_ASYNC16(dst, src) \
    asm volatile("cp.async.cg.shared.global [%0], [%1], 16;" :: "r"(dst), "l"(src) : "memory")
#define CP_COMMIT() asm volatile("cp.async.commit_group;" ::: "memory")

// ---------------- reductions ----------------
__device__ __forceinline__ float warpSum(float v){
#pragma unroll
    for (int o = 16; o; o >>= 1) v += __shfl_xor_sync(0xffffffffu, v, o);
    return v;
}
__device__ __forceinline__ float blockSum(float v, float* red){
    v = warpSum(v);
    int lane = threadIdx.x & 31, w = threadIdx.x >> 5;
    if (lane == 0) red[w] = v;
    __syncthreads();
    float r = 0.f;
#pragma unroll
    for (int i = 0; i < 8; i++) r += red[i];
    __syncthreads();
    return r;
}

// ---------------- 0: zero scale accumulator ----------------
__global__ void k_zero(){
    int i = blockIdx.x * 256 + threadIdx.x;
    if (i < NN) g_scale[i] = 0.f;
}

// ---------------- 1: rowsums of (adj + 0.5 I) -> g_sd ----------------
__global__ __launch_bounds__(256) void k_rowsum(const float* __restrict__ adj){
    __shared__ float red[8];
    int n = blockIdx.x;
    const float* row = adj + (size_t)n * NN;
    float s = 0.f;
    for (int m = threadIdx.x; m < NN; m += 256) s += row[m];
    if (threadIdx.x == 0) s += 0.5f;
    s = blockSum(s, red);
    if (threadIdx.x == 0) g_sd[n] = rsqrtf(s);
}

// ---------------- 2: double row-softmax of sym-normed adj, column sums --------
// 8 rows/block x 512 blocks for 2x parallelism vs 16x256.
__global__ __launch_bounds__(256) void k_scale(const float* __restrict__ adj){
    __shared__ float rowbuf[NN];
    __shared__ float acc[NN];
    __shared__ float red[8];
    int tid = threadIdx.x;
    for (int m = tid; m < NN; m += 256) acc[m] = 0.f;
    __syncthreads();
    for (int r = 0; r < 8; r++){
        int n = blockIdx.x * 8 + r;
        const float* row = adj + (size_t)n * NN;
        float sdn = g_sd[n];
        float ls = 0.f;
        for (int m = tid; m < NN; m += 256){
            float w = row[m] + ((m == n) ? 0.5f : 0.f);
            float e = fast_exp(sdn * w * g_sd[m]);
            rowbuf[m] = e; ls += e;
        }
        float inv = 1.f / blockSum(ls, red);
        float ls2 = 0.f;
        for (int m = tid; m < NN; m += 256){
            float e2 = fast_exp(rowbuf[m] * inv);
            rowbuf[m] = e2; ls2 += e2;
        }
        float inv2 = 1.f / blockSum(ls2, red);
        for (int m = tid; m < NN; m += 256) acc[m] += rowbuf[m] * inv2;
        __syncthreads();
    }
    for (int m = tid; m < NN; m += 256) atomicAdd(&g_scale[m], acc[m]);
}

// ---------------- 3: S = softmax(relu(E E^T)) -> fp16 -------------------------
// Register-capped to 3 CTAs/SM (was reg-limited to 2 at 97 regs).
#define DYN_ROWS 4
#define DYN_SMEM (DYN_ROWS * NN * 4)
__global__ __launch_bounds__(256, 3) void k_dyn(const float* __restrict__ E){
    extern __shared__ float rb[];                 // [DYN_ROWS][NN]
    __shared__ float er[DYN_ROWS][DE];
    __shared__ float red[8];
    int tid = threadIdx.x;
    int n0 = blockIdx.x * DYN_ROWS;
    if (tid < DYN_ROWS * DE) er[tid / DE][tid % DE] = E[(n0 + tid / DE) * DE + (tid % DE)];
    __syncthreads();
    float ls[DYN_ROWS] = {0.f, 0.f, 0.f, 0.f};
    for (int m = tid; m < NN; m += 256){
        const float4* ep = (const float4*)(E + (size_t)m * DE);
        float4 e0 = ep[0], e1 = ep[1], e2 = ep[2], e3 = ep[3];
        float em[16] = { e0.x,e0.y,e0.z,e0.w, e1.x,e1.y,e1.z,e1.w,
                         e2.x,e2.y,e2.z,e2.w, e3.x,e3.y,e3.z,e3.w };
#pragma unroll
        for (int r = 0; r < DYN_ROWS; r++){
            float d = 0.f;
#pragma unroll
            for (int k = 0; k < DE; k++) d += em[k] * er[r][k];
            float e = fast_exp(fmaxf(d, 0.f));
            rb[r * NN + m] = e;
            ls[r] += e;
        }
    }
    float inv[DYN_ROWS];
#pragma unroll
    for (int r = 0; r < DYN_ROWS; r++) inv[r] = 1.f / blockSum(ls[r], red);
#pragma unroll
    for (int r = 0; r < DYN_ROWS; r++){
        __half* oh = g_A + (size_t)(n0 + r) * NN;
        for (int m = tid; m < NN; m += 256)
            oh[m] = __float2half(rb[r * NN + m] * inv[r]);
    }
}

// ---------------- 4: x [B,N,C] -> B-operand [j=b*64+c][k] fp16 ----------------
__global__ __launch_bounds__(256) void k_xsplit(const float* __restrict__ x){
    __shared__ float xs[64][65];
    int b  = blockIdx.x >> 6;
    int kc = blockIdx.x & 63;
    int tid = threadIdx.x;
    const float* src = x + ((size_t)b * NN + kc * 64) * 64;
    for (int t = tid; t < 1024; t += 256){
        int kk = t >> 4, c4 = t & 15;
        float4 v = ((const float4*)src)[(size_t)kk * 16 + c4];
        xs[kk][c4 * 4 + 0] = v.x; xs[kk][c4 * 4 + 1] = v.y;
        xs[kk][c4 * 4 + 2] = v.z; xs[kk][c4 * 4 + 3] = v.w;
    }
    __syncthreads();
    int c = tid >> 2, q = tid & 3;
    union { __half h[16]; uint4 u[2]; } uh;
#pragma unroll
    for (int i = 0; i < 16; i++)
        uh.h[i] = __float2half(xs[q * 16 + i][c]);
    size_t off = ((size_t)(b * 64 + c)) * NN + kc * 64 + q * 16;
    *(uint4*)(g_B + off) = uh.u[0]; *(uint4*)(g_B + off + 8) = uh.u[1];
}

// ---------------- 5: per-node weights -> fp16 ---------------------------------
__global__ __launch_bounds__(256) void k_wgen(const float* __restrict__ E,
                                              const float* __restrict__ wp){
    __shared__ float wpc[DE * 512];
    __shared__ float es[128 * DE];
    int tid = threadIdx.x;
    int c0 = blockIdx.x * 512;
    int n0 = blockIdx.y * 128;
    for (int t = tid; t < DE * 512; t += 256){
        int d = t >> 9, j = t & 511;
        wpc[t] = wp[(size_t)d * 8192 + c0 + j];
    }
    for (int t = tid; t < 128 * DE; t += 256) es[t] = E[(size_t)n0 * DE + t];
    __syncthreads();
    for (int t = tid; t < 128 * 256; t += 256){
        int nl = t >> 8, j2 = (t & 255) * 2;
        float s0 = 0.f, s1 = 0.f;
#pragma unroll
        for (int d = 0; d < DE; d++){
            float e = es[nl * DE + d];
            s0 += e * wpc[d * 512 + j2];
            s1 += e * wpc[d * 512 + j2 + 1];
        }
        *(__half2*)&g_W16[(size_t)(n0 + nl) * 8192 + c0 + j2] =
            __floats2half2_rn(s0, s1);
    }
}

// ---------------- 6: HMMA GEMM  Y = S @ XT  (round-7 proven config) -----------
// Block 128x128, warp tile 32x64 (4x2 warps), K-chunk 32, 4-stage cp.async,
// 2 CTAs/SM. Rows padded to 80B -> ldmatrix conflict-free.
#define TILE_BYTES  10240
#define STAGE_BYTES (2 * TILE_BYTES)
#define GEMM_SMEM   (4 * STAGE_BYTES)

__global__ __launch_bounds__(256, 2) void k_gemm_mma(){
    extern __shared__ __align__(1024) char smem[];
    uint32_t sm = smem_u32(smem);
    int tid = threadIdx.x, wid = tid >> 5, lane = tid & 31;
    int bx = blockIdx.x, by = blockIdx.y;

    const char* pA = (const char*)g_A + (size_t)(by * 128) * (NN * 2);
    const char* pB = (const char*)g_B + (size_t)(bx * 128) * (NN * 2);

    int m0 = (wid & 3) * 32;
    int n0 = (wid >> 2) * 64;

    uint32_t a_off = (uint32_t)((m0 + (lane & 15)) * 80 + ((lane >> 4) << 4));
    uint32_t b_off = (uint32_t)((n0 + ((lane >> 4) << 3) + (lane & 7)) * 80
                                + (((lane >> 3) & 1) << 4));

    auto load_stage = [&](int buf, int kblk){
        uint32_t sbase = sm + (uint32_t)buf * STAGE_BYTES;
        size_t kb = (size_t)kblk * 64;             // 32 fp16 = 64B per row chunk
#pragma unroll
        for (int i = 0; i < 4; i++){
            int id = tid + i * 256;                // 0..1023
            int tile = id >> 9;                    // 0..1: A, B
            int r = (id >> 2) & 127;
            int c = id & 3;
            const char* gb = (tile == 0) ? pA : pB;
            const char* src = gb + (size_t)r * (NN * 2) + kb + (size_t)c * 16;
            uint32_t dst = sbase + (uint32_t)tile * TILE_BYTES + (uint32_t)(r * 80 + c * 16);
            CP_ASYNC16(dst, src);
        }
        CP_COMMIT();
    };

    float acc[2][8][4];
#pragma unroll
    for (int tm = 0; tm < 2; tm++)
#pragma unroll
        for (int nb = 0; nb < 8; nb++)
#pragma unroll
            for (int q = 0; q < 4; q++) acc[tm][nb][q] = 0.f;

    load_stage(0, 0);
    load_stage(1, 1);
    load_stage(2, 2);

    const int NIT = NN / 32;          // 128 iterations
    for (int s = 0; s < NIT; s++){
        if (s + 3 < NIT)      asm volatile("cp.async.wait_group 2;" ::: "memory");
        else if (s + 2 < NIT) asm volatile("cp.async.wait_group 1;" ::: "memory");
        else                  asm volatile("cp.async.wait_group 0;" ::: "memory");
        __syncthreads();
        if (s + 3 < NIT) load_stage((s + 3) & 3, s + 3);

        uint32_t st = sm + (uint32_t)(s & 3) * STAGE_BYTES;
        uint32_t aA = st + a_off;
        uint32_t aB = st + TILE_BYTES + b_off;
#pragma unroll
        for (int ks = 0; ks < 2; ks++){
            uint32_t ko = (uint32_t)(ks * 32);
            uint32_t Af[2][4], Bf[4][4];
            LDSM_X4(Af[0], aA + ko);
            LDSM_X4(Af[1], aA + 1280 + ko);         // +16 rows * 80B
#pragma unroll
            for (int p = 0; p < 4; p++)
                LDSM_X4(Bf[p], aB + (uint32_t)(p * 1280) + ko);
#pragma unroll
            for (int tm = 0; tm < 2; tm++)
#pragma unroll
                for (int nb = 0; nb < 8; nb++){
                    int p = nb >> 1, h = (nb & 1) * 2;
                    MMA16816(acc[tm][nb], Af[tm], Bf[p][h], Bf[p][h + 1]);
                }
        }
    }

    int gr = lane >> 2, gc = (lane & 3) * 2;
#pragma unroll
    for (int tm = 0; tm < 2; tm++){
        int row = by * 128 + m0 + tm * 16 + gr;
        float* y0 = g_Y + (size_t)row * NBJ + bx * 128 + n0 + gc;
        float* y1 = y0 + 8 * NBJ;
#pragma unroll
        for (int nb = 0; nb < 8; nb++){
            *(float2*)(y0 + nb * 8) = make_float2(acc[tm][nb][0], acc[tm][nb][1]);
            *(float2*)(y1 + nb * 8) = make_float2(acc[tm][nb][2], acc[tm][nb][3]);
        }
    }
}

// ---------------- 7: fused gconv + static branch ------------------------------
#define FIN_W   0
#define FIN_LW  8192
#define FIN_XS  (FIN_LW + 4096)
#define FIN_YS  (FIN_XS + 1024)
#define FIN_SMEM ((FIN_YS + 1024) * 4)
__global__ __launch_bounds__(256) void k_final(const float* __restrict__ x,
                                               const float* __restrict__ E,
                                               const float* __restrict__ bp,
                                               const float* __restrict__ lw,
                                               const float* __restrict__ lb,
                                               float* __restrict__ out){
    extern __shared__ float sf[];
    float* W  = sf + FIN_W;
    float* LW = sf + FIN_LW;
    float4* Xs = (float4*)(sf + FIN_XS);
    float4* Ys = (float4*)(sf + FIN_YS);
    __shared__ float bias_s[CC];
    __shared__ float lbs[CC];
    __shared__ float e_s[DE];
    int n = blockIdx.x, tid = threadIdx.x;
    if (tid < DE) e_s[tid] = E[(size_t)n * DE + tid];
    if (tid < CC) lbs[tid] = lb[tid];
    {
        const uint4* src = (const uint4*)(g_W16 + (size_t)n * 8192);
        for (int t = tid; t < 1024; t += 256){
            uint4 u = src[t];
            __half2* hp = (__half2*)&u;
            float* dst = W + t * 8;
#pragma unroll
            for (int q = 0; q < 4; q++){
                float2 f = __half22float2(hp[q]);
                dst[q * 2] = f.x; dst[q * 2 + 1] = f.y;
            }
        }
    }
    for (int idx = tid; idx < CC * CC; idx += 256){
        int o = idx & 63, i = idx >> 6;
        LW[i * 64 + o] = lw[o * 64 + i];
    }
    __syncthreads();
    if (tid < CC){
        float s = 0.f;
#pragma unroll
        for (int d = 0; d < DE; d++) s += e_s[d] * bp[d * 64 + tid];
        bias_s[tid] = s;
    }
    float scale_n = g_scale[n];
    int o = tid & 63, g = tid >> 6;
    for (int pass = 0; pass < 2; pass++){
        int bbase = pass * 16;
        __syncthreads();
        {
            int b = tid >> 4, i4 = tid & 15;
            Xs[b * 16 + i4] = *(const float4*)&x[((size_t)(bbase + b) * NN + n) * 64 + i4 * 4];
            Ys[b * 16 + i4] = *(const float4*)&g_Y[(size_t)n * NBJ + (bbase + b) * 64 + i4 * 4];
        }
        __syncthreads();
        float accg[4] = {0.f, 0.f, 0.f, 0.f};
        float accs[4] = {0.f, 0.f, 0.f, 0.f};
#pragma unroll 4
        for (int i4 = 0; i4 < 16; i4++){
            int ib = i4 * 4;
            float w00 = W[(ib + 0) * 64 + o], w01 = W[(ib + 1) * 64 + o];
            float w02 = W[(ib + 2) * 64 + o], w03 = W[(ib + 3) * 64 + o];
            float w10 = W[4096 + (ib + 0) * 64 + o], w11 = W[4096 + (ib + 1) * 64 + o];
            float w12 = W[4096 + (ib + 2) * 64 + o], w13 = W[4096 + (ib + 3) * 64 + o];
            float l0 = LW[(ib + 0) * 64 + o], l1 = LW[(ib + 1) * 64 + o];
            float l2 = LW[(ib + 2) * 64 + o], l3 = LW[(ib + 3) * 64 + o];
#pragma unroll
            for (int t = 0; t < 4; t++){
                float4 xv = Xs[(g + 4 * t) * 16 + i4];
                float4 yv = Ys[(g + 4 * t) * 16 + i4];
                float a = accg[t];
                a = fmaf(xv.x, w00, a); a = fmaf(xv.y, w01, a);
                a = fmaf(xv.z, w02, a); a = fmaf(xv.w, w03, a);
                a = fmaf(yv.x, w10, a); a = fmaf(yv.y, w11, a);
                a = fmaf(yv.z, w12, a); a = fmaf(yv.w, w13, a);
                accg[t] = a;
                float s = accs[t];
                s = fmaf(xv.x, l0, s); s = fmaf(xv.y, l1, s);
                s = fmaf(xv.z, l2, s); s = fmaf(xv.w, l3, s);
                accs[t] = s;
            }
        }
#pragma unroll
        for (int t = 0; t < 4; t++){
            int b = bbase + g + 4 * t;
            float xs = fmaf(scale_n, accs[t], lbs[o]);
            float sg = 1.f / (1.f + fast_exp(-xs));
            out[((size_t)b * NN + n) * 64 + o] = accg[t] + bias_s[o] + sg * xs;
        }
    }
}

// ---------------- launch ----------------
extern "C" void kernel_launch(void* const* d_in, const int* in_sizes, int n_in,
                              void* d_out, int out_size){
    const float* x   = (const float*)d_in[0];
    const float* E   = (const float*)d_in[1];
    const float* wp  = (const float*)d_in[2];
    const float* bp  = (const float*)d_in[3];
    const float* lw  = (const float*)d_in[4];
    const float* lb  = (const float*)d_in[5];
    const float* adj = (const float*)d_in[6];
    float* out = (float*)d_out;
    (void)in_sizes; (void)n_in; (void)out_size;

    cudaFuncSetAttribute(k_gemm_mma, cudaFuncAttributeMaxDynamicSharedMemorySize, GEMM_SMEM);
    cudaFuncSetAttribute(k_dyn,      cudaFuncAttributeMaxDynamicSharedMemorySize, DYN_SMEM);
    cudaFuncSetAttribute(k_final,    cudaFuncAttributeMaxDynamicSharedMemorySize, FIN_SMEM);

    k_zero    <<<16, 256>>>();
    k_rowsum  <<<NN, 256>>>(adj);
    k_scale   <<<NN / 8, 256>>>(adj);
    k_dyn     <<<NN / DYN_ROWS, 256, DYN_SMEM>>>(E);
    k_xsplit  <<<BB * 64, 256>>>(x);
    k_wgen    <<<dim3(16, 32), 256>>>(E, wp);
    k_gemm_mma<<<dim3(NBJ / 128, NN / 128), 256, GEMM_SMEM>>>();
    k_final   <<<NN, 256, FIN_SMEM>>>(x, E, bp, lw, lb, out);
}

// round 15
// speedup vs baseline: 1.1319x; 1.0798x over previous
#include <cuda_runtime.h>
#include <cuda_fp16.h>
#include <cstdint>

// ---------------- problem constants ----------------
#define NN    4096      // nodes
#define BB    32        // batch
#define CC    64        // channels in/out
#define DE    16        // embedding dim
#define NBJ   2048      // B*C  (columns of the big GEMM)

// ---------------- device scratch (no allocs allowed) ----------------
__device__ __align__(256) __half g_A [(size_t)NN * NN];    // fp16(S), 32 MB
__device__ __align__(256) __half g_B [(size_t)NBJ * NN];   // fp16(x^T) [j][k], 16 MB
__device__ __align__(256) float  g_Y [(size_t)NN * NBJ];   // S @ XT, 32 MB
__device__ __align__(256) __half g_W16[(size_t)NN * 8192]; // per-node weights fp16, 67 MB
__device__ float g_sd[NN];
__device__ float g_scale[NN];

// ---------------- fast exp: 6-FFMA exp2 poly + exponent bit trick -------------
__device__ __forceinline__ float fast_exp(float x){
    float t = fminf(fmaxf(x * 1.4426950408889634f, -125.f), 125.f);
    float fi = floorf(t);
    float f = t - fi;
    float p =            1.3393720e-3f;
    p = fmaf(p, f, 9.6181291e-3f);
    p = fmaf(p, f, 5.5504109e-2f);
    p = fmaf(p, f, 2.4022651e-1f);
    p = fmaf(p, f, 6.9314718e-1f);
    p = fmaf(p, f, 1.0f);
    return __int_as_float(__float_as_int(p) + ((int)fi << 23));
}

// ---------------- PTX helpers (base ISA: ldmatrix / mma.sync / cp.async) ------
__device__ __forceinline__ uint32_t smem_u32(const void* p){
    uint32_t a;
    asm("{ .reg .u64 t; cvta.to.shared.u64 t, %1; cvt.u32.u64 %0, t; }" : "=r"(a) : "l"(p));
    return a;
}
#define LDSM_X4(R, addr) \
    asm volatile("ldmatrix.sync.aligned.m8n8.x4.shared.b16 {%0,%1,%2,%3}, [%4];" \
        : "=r"((R)[0]), "=r"((R)[1]), "=r"((R)[2]), "=r"((R)[3]) : "r"(addr))
#define MMA16816(D, A, B0, B1) \
    asm volatile("mma.sync.aligned.m16n8k16.row.col.f32.f16.f16.f32 " \
        "{%0,%1,%2,%3}, {%4,%5,%6,%7}, {%8,%9}, {%0,%1,%2,%3};" \
        : "+f"((D)[0]), "+f"((D)[1]), "+f"((D)[2]), "+f"((D)[3]) \
        : "r"((A)[0]), "r"((A)[1]), "r"((A)[2]), "r"((A)[3]), "r"(B0), "r"(B1))
#define CP_ASYNC16(dst, src) \
    asm volatile("cp.async.cg.shared.global [%0], [%1], 16;" :: "r"(dst), "l"(src) : "memory")
#define CP_COMMIT() asm volatile("cp.async.commit_group;" ::: "memory")

// ---------------- reductions ----------------
__device__ __forceinline__ float warpSum(float v){
#pragma unroll
    for (int o = 16; o; o >>= 1) v += __shfl_xor_sync(0xffffffffu, v, o);
    return v;
}
__device__ __forceinline__ float blockSum(float v, float* red){
    v = warpSum(v);
    int lane = threadIdx.x & 31, w = threadIdx.x >> 5;
    if (lane == 0) red[w] = v;
    __syncthreads();
    float r = 0.f;
#pragma unroll
    for (int i = 0; i < 8; i++) r += red[i];
    __syncthreads();
    return r;
}

// ---------------- 0: zero scale accumulator ----------------
__global__ void k_zero(){
    int i = blockIdx.x * 256 + threadIdx.x;
    if (i < NN) g_scale[i] = 0.f;
}

// ---------------- 1: rowsums of (adj + 0.5 I) -> g_sd ----------------
__global__ __launch_bounds__(256) void k_rowsum(const float* __restrict__ adj){
    __shared__ float red[8];
    int n = blockIdx.x;
    const float* row = adj + (size_t)n * NN;
    float s = 0.f;
    for (int m = threadIdx.x; m < NN; m += 256) s += row[m];
    if (threadIdx.x == 0) s += 0.5f;
    s = blockSum(s, red);
    if (threadIdx.x == 0) g_sd[n] = rsqrtf(s);
}

// ---------------- 2: double row-softmax of sym-normed adj, column sums --------
// 8 rows/block x 512 blocks (proven in R11/R13).
__global__ __launch_bounds__(256) void k_scale(const float* __restrict__ adj){
    __shared__ float rowbuf[NN];
    __shared__ float acc[NN];
    __shared__ float red[8];
    int tid = threadIdx.x;
    for (int m = tid; m < NN; m += 256) acc[m] = 0.f;
    __syncthreads();
    for (int r = 0; r < 8; r++){
        int n = blockIdx.x * 8 + r;
        const float* row = adj + (size_t)n * NN;
        float sdn = g_sd[n];
        float ls = 0.f;
        for (int m = tid; m < NN; m += 256){
            float w = row[m] + ((m == n) ? 0.5f : 0.f);
            float e = fast_exp(sdn * w * g_sd[m]);
            rowbuf[m] = e; ls += e;
        }
        float inv = 1.f / blockSum(ls, red);
        float ls2 = 0.f;
        for (int m = tid; m < NN; m += 256){
            float e2 = fast_exp(rowbuf[m] * inv);
            rowbuf[m] = e2; ls2 += e2;
        }
        float inv2 = 1.f / blockSum(ls2, red);
        for (int m = tid; m < NN; m += 256) acc[m] += rowbuf[m] * inv2;
        __syncthreads();
    }
    for (int m = tid; m < NN; m += 256) atomicAdd(&g_scale[m], acc[m]);
}

// ---------------- 3: S = softmax(relu(E E^T)) -> fp16 -------------------------
// Reverted to R7 config (97 regs, 2 CTAs/SM) — the reg cap spilled and regressed.
#define DYN_ROWS 4
#define DYN_SMEM (DYN_ROWS * NN * 4)
__global__ __launch_bounds__(256) void k_dyn(const float* __restrict__ E){
    extern __shared__ float rb[];                 // [DYN_ROWS][NN]
    __shared__ float er[DYN_ROWS][DE];
    __shared__ float red[8];
    int tid = threadIdx.x;
    int n0 = blockIdx.x * DYN_ROWS;
    if (tid < DYN_ROWS * DE) er[tid / DE][tid % DE] = E[(n0 + tid / DE) * DE + (tid % DE)];
    __syncthreads();
    float ls[DYN_ROWS] = {0.f, 0.f, 0.f, 0.f};
    for (int m = tid; m < NN; m += 256){
        const float4* ep = (const float4*)(E + (size_t)m * DE);
        float4 e0 = ep[0], e1 = ep[1], e2 = ep[2], e3 = ep[3];
        float em[16] = { e0.x,e0.y,e0.z,e0.w, e1.x,e1.y,e1.z,e1.w,
                         e2.x,e2.y,e2.z,e2.w, e3.x,e3.y,e3.z,e3.w };
#pragma unroll
        for (int r = 0; r < DYN_ROWS; r++){
            float d = 0.f;
#pragma unroll
            for (int k = 0; k < DE; k++) d += em[k] * er[r][k];
            float e = fast_exp(fmaxf(d, 0.f));
            rb[r * NN + m] = e;
            ls[r] += e;
        }
    }
    float inv[DYN_ROWS];
#pragma unroll
    for (int r = 0; r < DYN_ROWS; r++) inv[r] = 1.f / blockSum(ls[r], red);
#pragma unroll
    for (int r = 0; r < DYN_ROWS; r++){
        __half* oh = g_A + (size_t)(n0 + r) * NN;
        for (int m = tid; m < NN; m += 256)
            oh[m] = __float2half(rb[r * NN + m] * inv[r]);
    }
}

// ---------------- 4: x [B,N,C] -> B-operand [j=b*64+c][k] fp16 ----------------
__global__ __launch_bounds__(256) void k_xsplit(const float* __restrict__ x){
    __shared__ float xs[64][65];
    int b  = blockIdx.x >> 6;
    int kc = blockIdx.x & 63;
    int tid = threadIdx.x;
    const float* src = x + ((size_t)b * NN + kc * 64) * 64;
    for (int t = tid; t < 1024; t += 256){
        int kk = t >> 4, c4 = t & 15;
        float4 v = ((const float4*)src)[(size_t)kk * 16 + c4];
        xs[kk][c4 * 4 + 0] = v.x; xs[kk][c4 * 4 + 1] = v.y;
        xs[kk][c4 * 4 + 2] = v.z; xs[kk][c4 * 4 + 3] = v.w;
    }
    __syncthreads();
    int c = tid >> 2, q = tid & 3;
    union { __half h[16]; uint4 u[2]; } uh;
#pragma unroll
    for (int i = 0; i < 16; i++)
        uh.h[i] = __float2half(xs[q * 16 + i][c]);
    size_t off = ((size_t)(b * 64 + c)) * NN + kc * 64 + q * 16;
    *(uint4*)(g_B + off) = uh.u[0]; *(uint4*)(g_B + off + 8) = uh.u[1];
}

// ---------------- 5: per-node weights -> fp16 ---------------------------------
__global__ __launch_bounds__(256) void k_wgen(const float* __restrict__ E,
                                              const float* __restrict__ wp){
    __shared__ float wpc[DE * 512];
    __shared__ float es[128 * DE];
    int tid = threadIdx.x;
    int c0 = blockIdx.x * 512;
    int n0 = blockIdx.y * 128;
    for (int t = tid; t < DE * 512; t += 256){
        int d = t >> 9, j = t & 511;
        wpc[t] = wp[(size_t)d * 8192 + c0 + j];
    }
    for (int t = tid; t < 128 * DE; t += 256) es[t] = E[(size_t)n0 * DE + t];
    __syncthreads();
    for (int t = tid; t < 128 * 256; t += 256){
        int nl = t >> 8, j2 = (t & 255) * 2;
        float s0 = 0.f, s1 = 0.f;
#pragma unroll
        for (int d = 0; d < DE; d++){
            float e = es[nl * DE + d];
            s0 += e * wpc[d * 512 + j2];
            s1 += e * wpc[d * 512 + j2 + 1];
        }
        *(__half2*)&g_W16[(size_t)(n0 + nl) * 8192 + c0 + j2] =
            __floats2half2_rn(s0, s1);
    }
}

// ---------------- 6: HMMA GEMM  Y = S @ XT  -----------------------------------
// Block 128x128, warp tile 32x64 (4x2 warps), K-chunk 64, 3-stage cp.async,
// 2 CTAs/SM. Rows 144B (128B data + 16B pad) -> ldmatrix conflict-free.
#define TILE_BYTES  18432           // 128 rows * 144B
#define STAGE_BYTES (2 * TILE_BYTES)
#define GEMM_SMEM   (3 * STAGE_BYTES)

__global__ __launch_bounds__(256, 2) void k_gemm_mma(){
    extern __shared__ __align__(1024) char smem[];
    uint32_t sm = smem_u32(smem);
    int tid = threadIdx.x, wid = tid >> 5, lane = tid & 31;
    int bx = blockIdx.x, by = blockIdx.y;

    const char* pA = (const char*)g_A + (size_t)(by * 128) * (NN * 2);
    const char* pB = (const char*)g_B + (size_t)(bx * 128) * (NN * 2);

    int m0 = (wid & 3) * 32;
    int n0 = (wid >> 2) * 64;

    uint32_t a_off = (uint32_t)((m0 + (lane & 15)) * 144 + ((lane >> 4) << 4));
    uint32_t b_off = (uint32_t)((n0 + ((lane >> 4) << 3) + (lane & 7)) * 144
                                + (((lane >> 3) & 1) << 4));

    auto load_stage = [&](int buf, int kblk){
        uint32_t sbase = sm + (uint32_t)buf * STAGE_BYTES;
        size_t kb = (size_t)kblk * 128;            // 64 fp16 = 128B per row chunk
#pragma unroll
        for (int i = 0; i < 8; i++){
            int id = tid + i * 256;                // 0..2047
            int tile = id >> 10;                   // 0..1: A, B
            int r = (id >> 3) & 127;
            int c = id & 7;
            const char* gb = (tile == 0) ? pA : pB;
            const char* src = gb + (size_t)r * (NN * 2) + kb + (size_t)c * 16;
            uint32_t dst = sbase + (uint32_t)tile * TILE_BYTES + (uint32_t)(r * 144 + c * 16);
            CP_ASYNC16(dst, src);
        }
        CP_COMMIT();
    };

    float acc[2][8][4];
#pragma unroll
    for (int tm = 0; tm < 2; tm++)
#pragma unroll
        for (int nb = 0; nb < 8; nb++)
#pragma unroll
            for (int q = 0; q < 4; q++) acc[tm][nb][q] = 0.f;

    load_stage(0, 0);
    load_stage(1, 1);

    const int NIT = NN / 64;          // 64 iterations
    for (int s = 0; s < NIT; s++){
        if (s + 2 < NIT) asm volatile("cp.async.wait_group 1;" ::: "memory");
        else             asm volatile("cp.async.wait_group 0;" ::: "memory");
        __syncthreads();
        if (s + 2 < NIT) load_stage((s + 2) % 3, s + 2);

        uint32_t st = sm + (uint32_t)(s % 3) * STAGE_BYTES;
        uint32_t aA = st + a_off;
        uint32_t aB = st + TILE_BYTES + b_off;
#pragma unroll
        for (int ks = 0; ks < 4; ks++){
            uint32_t ko = (uint32_t)(ks * 32);
            uint32_t Af[2][4], Bf[4][4];
            LDSM_X4(Af[0], aA + ko);
            LDSM_X4(Af[1], aA + 2304 + ko);         // +16 rows * 144B
#pragma unroll
            for (int p = 0; p < 4; p++)
                LDSM_X4(Bf[p], aB + (uint32_t)(p * 2304) + ko);
#pragma unroll
            for (int tm = 0; tm < 2; tm++)
#pragma unroll
                for (int nb = 0; nb < 8; nb++){
                    int p = nb >> 1, h = (nb & 1) * 2;
                    MMA16816(acc[tm][nb], Af[tm], Bf[p][h], Bf[p][h + 1]);
                }
        }
    }

    int gr = lane >> 2, gc = (lane & 3) * 2;
#pragma unroll
    for (int tm = 0; tm < 2; tm++){
        int row = by * 128 + m0 + tm * 16 + gr;
        float* y0 = g_Y + (size_t)row * NBJ + bx * 128 + n0 + gc;
        float* y1 = y0 + 8 * NBJ;
#pragma unroll
        for (int nb = 0; nb < 8; nb++){
            *(float2*)(y0 + nb * 8) = make_float2(acc[tm][nb][0], acc[tm][nb][1]);
            *(float2*)(y1 + nb * 8) = make_float2(acc[tm][nb][2], acc[tm][nb][3]);
        }
    }
}

// ---------------- 7: fused gconv + static branch ------------------------------
#define FIN_W   0
#define FIN_LW  8192
#define FIN_XS  (FIN_LW + 4096)
#define FIN_YS  (FIN_XS + 1024)
#define FIN_SMEM ((FIN_YS + 1024) * 4)
__global__ __launch_bounds__(256) void k_final(const float* __restrict__ x,
                                               const float* __restrict__ E,
                                               const float* __restrict__ bp,
                                               const float* __restrict__ lw,
                                               const float* __restrict__ lb,
                                               float* __restrict__ out){
    extern __shared__ float sf[];
    float* W  = sf + FIN_W;
    float* LW = sf + FIN_LW;
    float4* Xs = (float4*)(sf + FIN_XS);
    float4* Ys = (float4*)(sf + FIN_YS);
    __shared__ float bias_s[CC];
    __shared__ float lbs[CC];
    __shared__ float e_s[DE];
    int n = blockIdx.x, tid = threadIdx.x;
    if (tid < DE) e_s[tid] = E[(size_t)n * DE + tid];
    if (tid < CC) lbs[tid] = lb[tid];
    {
        const uint4* src = (const uint4*)(g_W16 + (size_t)n * 8192);
        for (int t = tid; t < 1024; t += 256){
            uint4 u = src[t];
            __half2* hp = (__half2*)&u;
            float* dst = W + t * 8;
#pragma unroll
            for (int q = 0; q < 4; q++){
                float2 f = __half22float2(hp[q]);
                dst[q * 2] = f.x; dst[q * 2 + 1] = f.y;
            }
        }
    }
    for (int idx = tid; idx < CC * CC; idx += 256){
        int o = idx & 63, i = idx >> 6;
        LW[i * 64 + o] = lw[o * 64 + i];
    }
    __syncthreads();
    if (tid < CC){
        float s = 0.f;
#pragma unroll
        for (int d = 0; d < DE; d++) s += e_s[d] * bp[d * 64 + tid];
        bias_s[tid] = s;
    }
    float scale_n = g_scale[n];
    int o = tid & 63, g = tid >> 6;
    for (int pass = 0; pass < 2; pass++){
        int bbase = pass * 16;
        __syncthreads();
        {
            int b = tid >> 4, i4 = tid & 15;
            Xs[b * 16 + i4] = *(const float4*)&x[((size_t)(bbase + b) * NN + n) * 64 + i4 * 4];
            Ys[b * 16 + i4] = *(const float4*)&g_Y[(size_t)n * NBJ + (bbase + b) * 64 + i4 * 4];
        }
        __syncthreads();
        float accg[4] = {0.f, 0.f, 0.f, 0.f};
        float accs[4] = {0.f, 0.f, 0.f, 0.f};
#pragma unroll 4
        for (int i4 = 0; i4 < 16; i4++){
            int ib = i4 * 4;
            float w00 = W[(ib + 0) * 64 + o], w01 = W[(ib + 1) * 64 + o];
            float w02 = W[(ib + 2) * 64 + o], w03 = W[(ib + 3) * 64 + o];
            float w10 = W[4096 + (ib + 0) * 64 + o], w11 = W[4096 + (ib + 1) * 64 + o];
            float w12 = W[4096 + (ib + 2) * 64 + o], w13 = W[4096 + (ib + 3) * 64 + o];
            float l0 = LW[(ib + 0) * 64 + o], l1 = LW[(ib + 1) * 64 + o];
            float l2 = LW[(ib + 2) * 64 + o], l3 = LW[(ib + 3) * 64 + o];
#pragma unroll
            for (int t = 0; t < 4; t++){
                float4 xv = Xs[(g + 4 * t) * 16 + i4];
                float4 yv = Ys[(g + 4 * t) * 16 + i4];
                float a = accg[t];
                a = fmaf(xv.x, w00, a); a = fmaf(xv.y, w01, a);
                a = fmaf(xv.z, w02, a); a = fmaf(xv.w, w03, a);
                a = fmaf(yv.x, w10, a); a = fmaf(yv.y, w11, a);
                a = fmaf(yv.z, w12, a); a = fmaf(yv.w, w13, a);
                accg[t] = a;
                float s = accs[t];
                s = fmaf(xv.x, l0, s); s = fmaf(xv.y, l1, s);
                s = fmaf(xv.z, l2, s); s = fmaf(xv.w, l3, s);
                accs[t] = s;
            }
        }
#pragma unroll
        for (int t = 0; t < 4; t++){
            int b = bbase + g + 4 * t;
            float xs = fmaf(scale_n, accs[t], lbs[o]);
            float sg = 1.f / (1.f + fast_exp(-xs));
            out[((size_t)b * NN + n) * 64 + o] = accg[t] + bias_s[o] + sg * xs;
        }
    }
}

// ---------------- launch ----------------
extern "C" void kernel_launch(void* const* d_in, const int* in_sizes, int n_in,
                              void* d_out, int out_size){
    const float* x   = (const float*)d_in[0];
    const float* E   = (const float*)d_in[1];
    const float* wp  = (const float*)d_in[2];
    const float* bp  = (const float*)d_in[3];
    const float* lw  = (const float*)d_in[4];
    const float* lb  = (const float*)d_in[5];
    const float* adj = (const float*)d_in[6];
    float* out = (float*)d_out;
    (void)in_sizes; (void)n_in; (void)out_size;

    cudaFuncSetAttribute(k_gemm_mma, cudaFuncAttributeMaxDynamicSharedMemorySize, GEMM_SMEM);
    cudaFuncSetAttribute(k_dyn,      cudaFuncAttributeMaxDynamicSharedMemorySize, DYN_SMEM);
    cudaFuncSetAttribute(k_final,    cudaFuncAttributeMaxDynamicSharedMemorySize, FIN_SMEM);

    k_zero    <<<16, 256>>>();
    k_rowsum  <<<NN, 256>>>(adj);
    k_scale   <<<NN / 8, 256>>>(adj);
    k_dyn     <<<NN / DYN_ROWS, 256, DYN_SMEM>>>(E);
    k_xsplit  <<<BB * 64, 256>>>(x);
    k_wgen    <<<dim3(16, 32), 256>>>(E, wp);
    k_gemm_mma<<<dim3(NBJ / 128, NN / 128), 256, GEMM_SMEM>>>();
    k_final   <<<NN, 256, FIN_SMEM>>>(x, E, bp, lw, lb, out);
}

// round 16
// speedup vs baseline: 1.4992x; 1.3244x over previous
#include <cuda_runtime.h>
#include <cuda_fp16.h>
#include <cstdint>

// ---------------- problem constants ----------------
#define NN    4096      // nodes
#define BB    32        // batch
#define CC    64        // channels in/out
#define DE    16        // embedding dim
#define NBJ   2048      // B*C  (columns of the big GEMM)

// ---------------- device scratch (no allocs allowed) ----------------
__device__ __align__(256) __half g_A [(size_t)NN * NN];    // fp16(S), 32 MB
__device__ __align__(256) __half g_B [(size_t)NBJ * NN];   // fp16(x^T) [j][k], 16 MB
__device__ __align__(256) __half g_Yh[(size_t)NN * NBJ];   // fp16(S @ XT), 16 MB
__device__ __align__(256) __half g_W16[(size_t)NN * 8192]; // per-node weights fp16, 67 MB
__device__ float g_sd[NN];
__device__ float g_scale[NN];

// ---------------- fast exp: 6-FFMA exp2 poly + exponent bit trick -------------
__device__ __forceinline__ float fast_exp(float x){
    float t = fminf(fmaxf(x * 1.4426950408889634f, -125.f), 125.f);
    float fi = floorf(t);
    float f = t - fi;
    float p =            1.3393720e-3f;
    p = fmaf(p, f, 9.6181291e-3f);
    p = fmaf(p, f, 5.5504109e-2f);
    p = fmaf(p, f, 2.4022651e-1f);
    p = fmaf(p, f, 6.9314718e-1f);
    p = fmaf(p, f, 1.0f);
    return __int_as_float(__float_as_int(p) + ((int)fi << 23));
}

// ---------------- PTX helpers (base ISA: ldmatrix / mma.sync / cp.async) ------
__device__ __forceinline__ uint32_t smem_u32(const void* p){
    uint32_t a;
    asm("{ .reg .u64 t; cvta.to.shared.u64 t, %1; cvt.u32.u64 %0, t; }" : "=r"(a) : "l"(p));
    return a;
}
#define LDSM_X4(R, addr) \
    asm volatile("ldmatrix.sync.aligned.m8n8.x4.shared.b16 {%0,%1,%2,%3}, [%4];" \
        : "=r"((R)[0]), "=r"((R)[1]), "=r"((R)[2]), "=r"((R)[3]) : "r"(addr))
#define LDSM_X4_T(R, addr) \
    asm volatile("ldmatrix.sync.aligned.m8n8.x4.trans.shared.b16 {%0,%1,%2,%3}, [%4];" \
        : "=r"((R)[0]), "=r"((R)[1]), "=r"((R)[2]), "=r"((R)[3]) : "r"(addr))
#define MMA16816(D, A, B0, B1) \
    asm volatile("mma.sync.aligned.m16n8k16.row.col.f32.f16.f16.f32 " \
        "{%0,%1,%2,%3}, {%4,%5,%6,%7}, {%8,%9}, {%0,%1,%2,%3};" \
        : "+f"((D)[0]), "+f"((D)[1]), "+f"((D)[2]), "+f"((D)[3]) \
        : "r"((A)[0]), "r"((A)[1]), "r"((A)[2]), "r"((A)[3]), "r"(B0), "r"(B1))
#define CP_ASYNC16(dst, src) \
    asm volatile("cp.async.cg.shared.global [%0], [%1], 16;" :: "r"(dst), "l"(src) : "memory")
#define CP_COMMIT() asm volatile("cp.async.commit_group;" ::: "memory")

// ---------------- reductions ----------------
__device__ __forceinline__ float warpSum(float v){
#pragma unroll
    for (int o = 16; o; o >>= 1) v += __shfl_xor_sync(0xffffffffu, v, o);
    return v;
}
__device__ __forceinline__ float blockSum(float v, float* red){
    v = warpSum(v);
    int lane = threadIdx.x & 31, w = threadIdx.x >> 5;
    if (lane == 0) red[w] = v;
    __syncthreads();
    float r = 0.f;
#pragma unroll
    for (int i = 0; i < 8; i++) r += red[i];
    __syncthreads();
    return r;
}

// ---------------- 0: zero scale accumulator ----------------
__global__ void k_zero(){
    int i = blockIdx.x * 256 + threadIdx.x;
    if (i < NN) g_scale[i] = 0.f;
}

// ---------------- 1: rowsums of (adj + 0.5 I) -> g_sd ----------------
__global__ __launch_bounds__(256) void k_rowsum(const float* __restrict__ adj){
    __shared__ float red[8];
    int n = blockIdx.x;
    const float* row = adj + (size_t)n * NN;
    float s = 0.f;
    for (int m = threadIdx.x; m < NN; m += 256) s += row[m];
    if (threadIdx.x == 0) s += 0.5f;
    s = blockSum(s, red);
    if (threadIdx.x == 0) g_sd[n] = rsqrtf(s);
}

// ---------------- 2: double row-softmax of sym-normed adj, column sums --------
__global__ __launch_bounds__(256) void k_scale(const float* __restrict__ adj){
    __shared__ float rowbuf[NN];
    __shared__ float acc[NN];
    __shared__ float red[8];
    int tid = threadIdx.x;
    for (int m = tid; m < NN; m += 256) acc[m] = 0.f;
    __syncthreads();
    for (int r = 0; r < 8; r++){
        int n = blockIdx.x * 8 + r;
        const float* row = adj + (size_t)n * NN;
        float sdn = g_sd[n];
        float ls = 0.f;
        for (int m = tid; m < NN; m += 256){
            float w = row[m] + ((m == n) ? 0.5f : 0.f);
            float e = fast_exp(sdn * w * g_sd[m]);
            rowbuf[m] = e; ls += e;
        }
        float inv = 1.f / blockSum(ls, red);
        float ls2 = 0.f;
        for (int m = tid; m < NN; m += 256){
            float e2 = fast_exp(rowbuf[m] * inv);
            rowbuf[m] = e2; ls2 += e2;
        }
        float inv2 = 1.f / blockSum(ls2, red);
        for (int m = tid; m < NN; m += 256) acc[m] += rowbuf[m] * inv2;
        __syncthreads();
    }
    for (int m = tid; m < NN; m += 256) atomicAdd(&g_scale[m], acc[m]);
}

// ---------------- 3: S = softmax(relu(E E^T)) -> fp16 -------------------------
#define DYN_ROWS 4
#define DYN_SMEM (DYN_ROWS * NN * 4)
__global__ __launch_bounds__(256) void k_dyn(const float* __restrict__ E){
    extern __shared__ float rb[];                 // [DYN_ROWS][NN]
    __shared__ float er[DYN_ROWS][DE];
    __shared__ float red[8];
    int tid = threadIdx.x;
    int n0 = blockIdx.x * DYN_ROWS;
    if (tid < DYN_ROWS * DE) er[tid / DE][tid % DE] = E[(n0 + tid / DE) * DE + (tid % DE)];
    __syncthreads();
    float ls[DYN_ROWS] = {0.f, 0.f, 0.f, 0.f};
    for (int m = tid; m < NN; m += 256){
        const float4* ep = (const float4*)(E + (size_t)m * DE);
        float4 e0 = ep[0], e1 = ep[1], e2 = ep[2], e3 = ep[3];
        float em[16] = { e0.x,e0.y,e0.z,e0.w, e1.x,e1.y,e1.z,e1.w,
                         e2.x,e2.y,e2.z,e2.w, e3.x,e3.y,e3.z,e3.w };
#pragma unroll
        for (int r = 0; r < DYN_ROWS; r++){
            float d = 0.f;
#pragma unroll
            for (int k = 0; k < DE; k++) d += em[k] * er[r][k];
            float e = fast_exp(fmaxf(d, 0.f));
            rb[r * NN + m] = e;
            ls[r] += e;
        }
    }
    float inv[DYN_ROWS];
#pragma unroll
    for (int r = 0; r < DYN_ROWS; r++) inv[r] = 1.f / blockSum(ls[r], red);
#pragma unroll
    for (int r = 0; r < DYN_ROWS; r++){
        __half* oh = g_A + (size_t)(n0 + r) * NN;
        for (int m = tid; m < NN; m += 256)
            oh[m] = __float2half(rb[r * NN + m] * inv[r]);
    }
}

// ---------------- 4: x [B,N,C] -> B-operand [j=b*64+c][k] fp16 ----------------
__global__ __launch_bounds__(256) void k_xsplit(const float* __restrict__ x){
    __shared__ float xs[64][65];
    int b  = blockIdx.x >> 6;
    int kc = blockIdx.x & 63;
    int tid = threadIdx.x;
    const float* src = x + ((size_t)b * NN + kc * 64) * 64;
    for (int t = tid; t < 1024; t += 256){
        int kk = t >> 4, c4 = t & 15;
        float4 v = ((const float4*)src)[(size_t)kk * 16 + c4];
        xs[kk][c4 * 4 + 0] = v.x; xs[kk][c4 * 4 + 1] = v.y;
        xs[kk][c4 * 4 + 2] = v.z; xs[kk][c4 * 4 + 3] = v.w;
    }
    __syncthreads();
    int c = tid >> 2, q = tid & 3;
    union { __half h[16]; uint4 u[2]; } uh;
#pragma unroll
    for (int i = 0; i < 16; i++)
        uh.h[i] = __float2half(xs[q * 16 + i][c]);
    size_t off = ((size_t)(b * 64 + c)) * NN + kc * 64 + q * 16;
    *(uint4*)(g_B + off) = uh.u[0]; *(uint4*)(g_B + off + 8) = uh.u[1];
}

// ---------------- 5: per-node weights -> fp16 ---------------------------------
__global__ __launch_bounds__(256) void k_wgen(const float* __restrict__ E,
                                              const float* __restrict__ wp){
    __shared__ float wpc[DE * 512];
    __shared__ float es[128 * DE];
    int tid = threadIdx.x;
    int c0 = blockIdx.x * 512;
    int n0 = blockIdx.y * 128;
    for (int t = tid; t < DE * 512; t += 256){
        int d = t >> 9, j = t & 511;
        wpc[t] = wp[(size_t)d * 8192 + c0 + j];
    }
    for (int t = tid; t < 128 * DE; t += 256) es[t] = E[(size_t)n0 * DE + t];
    __syncthreads();
    for (int t = tid; t < 128 * 256; t += 256){
        int nl = t >> 8, j2 = (t & 255) * 2;
        float s0 = 0.f, s1 = 0.f;
#pragma unroll
        for (int d = 0; d < DE; d++){
            float e = es[nl * DE + d];
            s0 += e * wpc[d * 512 + j2];
            s1 += e * wpc[d * 512 + j2 + 1];
        }
        *(__half2*)&g_W16[(size_t)(n0 + nl) * 8192 + c0 + j2] =
            __floats2half2_rn(s0, s1);
    }
}

// ---------------- 6: HMMA GEMM  Y = S @ XT  (K-chunk 64, 3-stage) -------------
// Block 128x128, warp tile 32x64 (4x2 warps), 2 CTAs/SM. Rows 144B.
// Epilogue stores Y as fp16 (g_Yh).
#define TILE_BYTES  18432           // 128 rows * 144B
#define STAGE_BYTES (2 * TILE_BYTES)
#define GEMM_SMEM   (3 * STAGE_BYTES)

__global__ __launch_bounds__(256, 2) void k_gemm_mma(){
    extern __shared__ __align__(1024) char smem[];
    uint32_t sm = smem_u32(smem);
    int tid = threadIdx.x, wid = tid >> 5, lane = tid & 31;
    int bx = blockIdx.x, by = blockIdx.y;

    const char* pA = (const char*)g_A + (size_t)(by * 128) * (NN * 2);
    const char* pB = (const char*)g_B + (size_t)(bx * 128) * (NN * 2);

    int m0 = (wid & 3) * 32;
    int n0 = (wid >> 2) * 64;

    uint32_t a_off = (uint32_t)((m0 + (lane & 15)) * 144 + ((lane >> 4) << 4));
    uint32_t b_off = (uint32_t)((n0 + ((lane >> 4) << 3) + (lane & 7)) * 144
                                + (((lane >> 3) & 1) << 4));

    auto load_stage = [&](int buf, int kblk){
        uint32_t sbase = sm + (uint32_t)buf * STAGE_BYTES;
        size_t kb = (size_t)kblk * 128;            // 64 fp16 = 128B per row chunk
#pragma unroll
        for (int i = 0; i < 8; i++){
            int id = tid + i * 256;                // 0..2047
            int tile = id >> 10;                   // 0..1: A, B
            int r = (id >> 3) & 127;
            int c = id & 7;
            const char* gb = (tile == 0) ? pA : pB;
            const char* src = gb + (size_t)r * (NN * 2) + kb + (size_t)c * 16;
            uint32_t dst = sbase + (uint32_t)tile * TILE_BYTES + (uint32_t)(r * 144 + c * 16);
            CP_ASYNC16(dst, src);
        }
        CP_COMMIT();
    };

    float acc[2][8][4];
#pragma unroll
    for (int tm = 0; tm < 2; tm++)
#pragma unroll
        for (int nb = 0; nb < 8; nb++)
#pragma unroll
            for (int q = 0; q < 4; q++) acc[tm][nb][q] = 0.f;

    load_stage(0, 0);
    load_stage(1, 1);

    const int NIT = NN / 64;          // 64 iterations
    for (int s = 0; s < NIT; s++){
        if (s + 2 < NIT) asm volatile("cp.async.wait_group 1;" ::: "memory");
        else             asm volatile("cp.async.wait_group 0;" ::: "memory");
        __syncthreads();
        if (s + 2 < NIT) load_stage((s + 2) % 3, s + 2);

        uint32_t st = sm + (uint32_t)(s % 3) * STAGE_BYTES;
        uint32_t aA = st + a_off;
        uint32_t aB = st + TILE_BYTES + b_off;
#pragma unroll
        for (int ks = 0; ks < 4; ks++){
            uint32_t ko = (uint32_t)(ks * 32);
            uint32_t Af[2][4], Bf[4][4];
            LDSM_X4(Af[0], aA + ko);
            LDSM_X4(Af[1], aA + 2304 + ko);         // +16 rows * 144B
#pragma unroll
            for (int p = 0; p < 4; p++)
                LDSM_X4(Bf[p], aB + (uint32_t)(p * 2304) + ko);
#pragma unroll
            for (int tm = 0; tm < 2; tm++)
#pragma unroll
                for (int nb = 0; nb < 8; nb++){
                    int p = nb >> 1, h = (nb & 1) * 2;
                    MMA16816(acc[tm][nb], Af[tm], Bf[p][h], Bf[p][h + 1]);
                }
        }
    }

    int gr = lane >> 2, gc = (lane & 3) * 2;
#pragma unroll
    for (int tm = 0; tm < 2; tm++){
        int row = by * 128 + m0 + tm * 16 + gr;
        __half* y0 = g_Yh + (size_t)row * NBJ + bx * 128 + n0 + gc;
        __half* y1 = y0 + 8 * NBJ;
#pragma unroll
        for (int nb = 0; nb < 8; nb++){
            *(__half2*)(y0 + nb * 8) = __floats2half2_rn(acc[tm][nb][0], acc[tm][nb][1]);
            *(__half2*)(y1 + nb * 8) = __floats2half2_rn(acc[tm][nb][2], acc[tm][nb][3]);
        }
    }
}

// ---------------- 7: fused gconv + static branch — tensor-core version --------
// One block per node. out[b][n][o] = (A @ W)[b][o] + bias[o] + sigmoid(xs)*xs,
// A = [x fp16 | Yh fp16] (32 x 128), W = g_W16[n] ([i][o] K-major -> ldsm.trans),
// xs = scale[n]*(x @ lw^T)[b][o] + lb[o], lw [o][i] -> GEMM-style non-trans ldsm.
__global__ __launch_bounds__(256) void k_final(const float* __restrict__ x,
                                               const float* __restrict__ E,
                                               const float* __restrict__ bp,
                                               const float* __restrict__ lw,
                                               const float* __restrict__ lb,
                                               float* __restrict__ out){
    __shared__ __align__(16) char smA[32 * 272];    // A: 32 rows x (256B data + 16 pad)
    __shared__ __align__(16) char smW[128 * 144];   // W: 128 i-rows x (128B + 16 pad)
    __shared__ __align__(16) char smL[64 * 144];    // lw fp16: 64 o-rows x (128B + 16 pad)
    __shared__ float bias_s[CC];
    __shared__ float lbs[CC];
    __shared__ float e_s[DE];
    int n = blockIdx.x, tid = threadIdx.x;
    int wid = tid >> 5, lane = tid & 31;

    if (tid < DE) e_s[tid] = E[(size_t)n * DE + tid];
    if (tid < CC) lbs[tid] = lb[tid];

    // W row (16 KB) -> smem, 144B rows
    {
        const uint4* src = (const uint4*)(g_W16 + (size_t)n * 8192);
        for (int t = tid; t < 1024; t += 256){
            int r = t >> 3, c = t & 7;
            *(uint4*)(smW + r * 144 + c * 16) = src[t];
        }
    }
    // lw fp32 [o][i] -> fp16 smem, 144B rows
    for (int t = tid; t < 1024; t += 256){
        int r = t >> 4, f4 = t & 15;
        float4 v = ((const float4*)lw)[r * 16 + f4];
        __half2* d = (__half2*)(smA /*dummy*/);
        (void)d;
        __half2 h0 = __floats2half2_rn(v.x, v.y);
        __half2 h1 = __floats2half2_rn(v.z, v.w);
        *(__half2*)(smL + r * 144 + f4 * 8)     = h0;
        *(__half2*)(smL + r * 144 + f4 * 8 + 4) = h1;
    }
    // x rows -> A cols 0..63 (fp16)
    for (int t = tid; t < 512; t += 256){
        int b = t >> 4, f4 = t & 15;
        float4 v = ((const float4*)(x + ((size_t)b * NN + n) * 64))[f4];
        __half2 h0 = __floats2half2_rn(v.x, v.y);
        __half2 h1 = __floats2half2_rn(v.z, v.w);
        *(__half2*)(smA + b * 272 + f4 * 8)     = h0;
        *(__half2*)(smA + b * 272 + f4 * 8 + 4) = h1;
    }
    // Yh row -> A cols 64..127 (raw fp16 copy)
    {
        const uint4* src = (const uint4*)(g_Yh + (size_t)n * NBJ);
        for (int t = tid; t < 256; t += 256){
            int b = t >> 3, c = t & 7;
            *(uint4*)(smA + b * 272 + 128 + c * 16) = src[t];
        }
    }
    __syncthreads();
    if (tid < CC){
        float s = 0.f;
#pragma unroll
        for (int d = 0; d < DE; d++) s += e_s[d] * bp[d * 64 + tid];
        bias_s[tid] = s;
    }

    // warp layout: 2 m-tiles (16 b) x 4 n-tiles (16 o)
    int mw = wid & 1, nw = wid >> 1;
    int m0 = mw * 16, n0w = nw * 16;
    uint32_t aBase = smem_u32(smA) + (uint32_t)((m0 + (lane & 15)) * 272 + ((lane >> 4) << 4));
    uint32_t wBase = smem_u32(smW) + (uint32_t)((lane & 15) * 144 + n0w * 2 + ((lane >> 4) << 4));
    uint32_t lBase = smem_u32(smL) + (uint32_t)((n0w + ((lane >> 4) << 3) + (lane & 7)) * 144
                                                + (((lane >> 3) & 1) << 4));
    float ag[2][4] = {{0.f,0.f,0.f,0.f},{0.f,0.f,0.f,0.f}};
    float as_[2][4] = {{0.f,0.f,0.f,0.f},{0.f,0.f,0.f,0.f}};
    __syncthreads();
#pragma unroll
    for (int ks = 0; ks < 8; ks++){
        uint32_t Af[4], Wf[4];
        LDSM_X4(Af, aBase + (uint32_t)(ks * 32));
        LDSM_X4_T(Wf, wBase + (uint32_t)(ks * 16 * 144));
        MMA16816(ag[0], Af, Wf[0], Wf[1]);
        MMA16816(ag[1], Af, Wf[2], Wf[3]);
        if (ks < 4){
            uint32_t Lf[4];
            LDSM_X4(Lf, lBase + (uint32_t)(ks * 32));
            MMA16816(as_[0], Af, Lf[0], Lf[1]);
            MMA16816(as_[1], Af, Lf[2], Lf[3]);
        }
    }

    float scale_n = g_scale[n];
    int gr = lane >> 2, gc = (lane & 3) * 2;
#pragma unroll
    for (int oct = 0; oct < 2; oct++){
        int o = n0w + oct * 8 + gc;
        float bi = bias_s[o],     bi1 = bias_s[o + 1];
        float lb0 = lbs[o],       lb1 = lbs[o + 1];
#pragma unroll
        for (int half = 0; half < 2; half++){
            int b = m0 + half * 8 + gr;
            float g0 = ag[oct][half * 2 + 0], g1 = ag[oct][half * 2 + 1];
            float s0 = as_[oct][half * 2 + 0], s1 = as_[oct][half * 2 + 1];
            float xs0 = fmaf(scale_n, s0, lb0);
            float xs1 = fmaf(scale_n, s1, lb1);
            float sg0 = 1.f / (1.f + fast_exp(-xs0));
            float sg1 = 1.f / (1.f + fast_exp(-xs1));
            float2 v = make_float2(g0 + bi + sg0 * xs0, g1 + bi1 + sg1 * xs1);
            *(float2*)&out[((size_t)b * NN + n) * 64 + o] = v;
        }
    }
}

// ---------------- launch ----------------
extern "C" void kernel_launch(void* const* d_in, const int* in_sizes, int n_in,
                              void* d_out, int out_size){
    const float* x   = (const float*)d_in[0];
    const float* E   = (const float*)d_in[1];
    const float* wp  = (const float*)d_in[2];
    const float* bp  = (const float*)d_in[3];
    const float* lw  = (const float*)d_in[4];
    const float* lb  = (const float*)d_in[5];
    const float* adj = (const float*)d_in[6];
    float* out = (float*)d_out;
    (void)in_sizes; (void)n_in; (void)out_size;

    cudaFuncSetAttribute(k_gemm_mma, cudaFuncAttributeMaxDynamicSharedMemorySize, GEMM_SMEM);
    cudaFuncSetAttribute(k_dyn,      cudaFuncAttributeMaxDynamicSharedMemorySize, DYN_SMEM);

    k_zero    <<<16, 256>>>();
    k_rowsum  <<<NN, 256>>>(adj);
    k_scale   <<<NN / 8, 256>>>(adj);
    k_dyn     <<<NN / DYN_ROWS, 256, DYN_SMEM>>>(E);
    k_xsplit  <<<BB * 64, 256>>>(x);
    k_wgen    <<<dim3(16, 32), 256>>>(E, wp);
    k_gemm_mma<<<dim3(NBJ / 128, NN / 128), 256, GEMM_SMEM>>>();
    k_final   <<<NN, 256>>>(x, E, bp, lw, lb, out);
}